// round 9
// baseline (speedup 1.0000x reference)
#include <cuda_runtime.h>
#include <cstdint>

#define N_NODES 100000
#define N_EDGES 1600000
#define IN_F    128
#define OUT_F   32

// Scratch (__device__ globals; no allocation anywhere in this file).
__device__ int   g_deg[N_NODES];
__device__ float g_Wt [IN_F * OUT_F];      // W transposed: [k][f]
__device__ float g_hs [N_NODES * OUT_F];   // h * dis[node]  (src-normalized message)
__device__ float g_acc[N_NODES * OUT_F];   // accumulator (init = self-loop term h*dis)

// ---------------------------------------------------------------------------
__global__ void k_deg_init() {
    int i = blockIdx.x * blockDim.x + threadIdx.x;
    if (i < N_NODES) g_deg[i] = 1;                 // self loop
}

__global__ void k_deg_count(const int* __restrict__ ei) {
    int e = blockIdx.x * blockDim.x + threadIdx.x;
    if (e < N_EDGES) atomicAdd(&g_deg[ei[N_EDGES + e]], 1);
}

// One-shot W transpose: strided read paid ONCE (not per linear block).
__global__ void k_wt(const float* __restrict__ W) {
    int idx = blockIdx.x * blockDim.x + threadIdx.x;   // idx = k*32 + f
    if (idx < IN_F * OUT_F) {
        int k = idx >> 5;
        int f = idx & 31;
        g_Wt[idx] = W[f * IN_F + k];
    }
}

// ---------------------------------------------------------------------------
// K4: h = x @ W^T ; g_hs = g_acc = h * rsqrt(deg).
// W loaded from pre-transposed g_Wt (coalesced float4, conflict-free STS).
// x tile staged via cp.async. 8 warps; warp register-blocks 8 nodes; lane = f.
#define NODES_PER_WARP 8
#define NODES_PER_BLK  64

#define CP_ASYNC16(saddr, gptr) \
    asm volatile("cp.async.cg.shared.global [%0], [%1], 16;" \
                 :: "r"(saddr), "l"(gptr) : "memory")

__global__ __launch_bounds__(256) void k_linear(const float* __restrict__ x) {
    __shared__ float sWt[IN_F][OUT_F];              // [k][f]
    __shared__ float sx[NODES_PER_BLK][IN_F];       // 32KB tile

    int tid = threadIdx.x;
    int node0 = blockIdx.x * NODES_PER_BLK;
    bool full = (node0 + NODES_PER_BLK <= N_NODES);

    // Stage x tile (2048 float4). cp.async for full blocks; guarded fallback for tail.
    const float4* xg = (const float4*)(x + (size_t)node0 * IN_F);
    float4* sx4 = (float4*)sx;
    if (full) {
        unsigned sbase;
        asm("{ .reg .u64 t; cvta.to.shared.u64 t, %1; cvt.u32.u64 %0, t; }"
            : "=r"(sbase) : "l"(sx4));
        #pragma unroll
        for (int i = 0; i < 8; i++) {
            int idx = tid + i * 256;
            CP_ASYNC16(sbase + idx * 16, xg + idx);
        }
        asm volatile("cp.async.commit_group;" ::: "memory");
    } else {
        #pragma unroll
        for (int i = 0; i < 8; i++) {
            int idx = tid + i * 256;
            sx4[idx] = (node0 + (idx >> 5) < N_NODES) ? xg[idx]
                                                      : make_float4(0.f, 0.f, 0.f, 0.f);
        }
    }

    // W: coalesced float4 copy from g_Wt (L2-resident), conflict-free STS.
    {
        const float4* Wt4 = (const float4*)g_Wt;
        float4* sWt4 = (float4*)sWt;
        #pragma unroll
        for (int i = 0; i < 4; i++)                 // 1024 float4 / 256 threads
            sWt4[tid + i * 256] = Wt4[tid + i * 256];
    }

    if (full) asm volatile("cp.async.wait_group 0;" ::: "memory");
    __syncthreads();

    int warp = tid >> 5;
    int f    = tid & 31;
    int nb   = warp * NODES_PER_WARP;

    float acc[NODES_PER_WARP];
    #pragma unroll
    for (int n = 0; n < NODES_PER_WARP; n++) acc[n] = 0.0f;

    #pragma unroll 8
    for (int k4 = 0; k4 < IN_F / 4; k4++) {
        int k = k4 * 4;
        float w0 = sWt[k + 0][f];
        float w1 = sWt[k + 1][f];
        float w2 = sWt[k + 2][f];
        float w3 = sWt[k + 3][f];
        #pragma unroll
        for (int n = 0; n < NODES_PER_WARP; n++) {
            float4 xv = *(const float4*)&sx[nb + n][k];   // broadcast LDS.128
            acc[n] = fmaf(xv.x, w0, acc[n]);
            acc[n] = fmaf(xv.y, w1, acc[n]);
            acc[n] = fmaf(xv.z, w2, acc[n]);
            acc[n] = fmaf(xv.w, w3, acc[n]);
        }
    }

    #pragma unroll
    for (int n = 0; n < NODES_PER_WARP; n++) {
        int node = node0 + nb + n;
        if (node < N_NODES) {
            float d  = rsqrtf((float)g_deg[node]);
            float hd = acc[n] * d;
            g_hs [node * OUT_F + f] = hd;
            g_acc[node * OUT_F + f] = hd;           // self-loop term (dst norm at finalize)
        }
    }
}

// ---------------------------------------------------------------------------
// K5: edge scatter. 8 lanes per edge-pair slot; each slot handles edges
// (e, e + N_EDGES/2) for MLP=2 on the gathers. Pure gather + RED.
#define HALF_E (N_EDGES / 2)
__global__ __launch_bounds__(256) void k_scatter(const int* __restrict__ ei) {
    int gtid = blockIdx.x * blockDim.x + threadIdx.x;
    int e0 = gtid >> 3;                  // [0, HALF_E)
    int fq = (gtid & 7) * 4;
    int e1 = e0 + HALF_E;

    int src0 = ei[e0];
    int dst0 = ei[N_EDGES + e0];
    int src1 = ei[e1];
    int dst1 = ei[N_EDGES + e1];

    float4 v0 = *(const float4*)(g_hs + src0 * OUT_F + fq);  // both gathers in flight
    float4 v1 = *(const float4*)(g_hs + src1 * OUT_F + fq);

    float* a0 = g_acc + dst0 * OUT_F + fq;
    asm volatile("red.global.add.v4.f32 [%0], {%1, %2, %3, %4};"
                 :: "l"(a0), "f"(v0.x), "f"(v0.y), "f"(v0.z), "f"(v0.w) : "memory");
    float* a1 = g_acc + dst1 * OUT_F + fq;
    asm volatile("red.global.add.v4.f32 [%0], {%1, %2, %3, %4};"
                 :: "l"(a1), "f"(v1.x), "f"(v1.y), "f"(v1.z), "f"(v1.w) : "memory");
}

// ---------------------------------------------------------------------------
// K6: out = g_acc * dis[node] + b   (plain coalesced float4 stores to d_out)
__global__ __launch_bounds__(256) void k_finalize(const float* __restrict__ b,
                                                  float* __restrict__ out) {
    int i = blockIdx.x * blockDim.x + threadIdx.x;    // float4 index
    if (i < N_NODES * OUT_F / 4) {
        int node = i >> 3;
        float d  = rsqrtf((float)g_deg[node]);
        float4 a = *((const float4*)g_acc + i);
        int fb = (i * 4) & (OUT_F - 1);
        a.x = fmaf(a.x, d, b[fb + 0]);
        a.y = fmaf(a.y, d, b[fb + 1]);
        a.z = fmaf(a.z, d, b[fb + 2]);
        a.w = fmaf(a.w, d, b[fb + 3]);
        *((float4*)out + i) = a;
    }
}

// ---------------------------------------------------------------------------
extern "C" void kernel_launch(void* const* d_in, const int* in_sizes, int n_in,
                              void* d_out, int out_size) {
    const float* x  = (const float*)d_in[0];
    const int*   ei = (const int*)d_in[1];     // int32 (harness downcasts int64)
    const float* W  = (const float*)d_in[2];
    const float* b  = (const float*)d_in[3];
    float*       out = (float*)d_out;

    (void)in_sizes; (void)n_in; (void)out_size;

    k_deg_init <<<(N_NODES + 255) / 256, 256>>>();
    k_wt       <<<(IN_F * OUT_F + 255) / 256, 256>>>(W);
    k_deg_count<<<(N_EDGES + 255) / 256, 256>>>(ei);
    k_linear   <<<(N_NODES + NODES_PER_BLK - 1) / NODES_PER_BLK, 256>>>(x);
    k_scatter  <<<(HALF_E * 8) / 256, 256>>>(ei);
    k_finalize <<<(N_NODES * OUT_F / 4 + 255) / 256, 256>>>(b, out);
}

// round 10
// speedup vs baseline: 1.4186x; 1.4186x over previous
#include <cuda_runtime.h>
#include <cstdint>

#define N_NODES 100000
#define N_EDGES 1600000
#define IN_F    128
#define OUT_F   32

typedef unsigned long long u64;

// Scratch (__device__ globals; no allocation anywhere in this file).
__device__ int   g_deg[N_NODES];
__device__ u64   g_W2 [(IN_F / 2) * OUT_F];   // packed W pairs: [k2][f] = (w[2k2],w[2k2+1])
__device__ float g_hs [N_NODES * OUT_F];      // h * dis[node]  (src-normalized message)
__device__ float g_acc[N_NODES * OUT_F];      // accumulator (init = self-loop term)

// ---------------------------------------------------------------------------
// K1: deg=1 (self loop) + one-shot W pair packing (strided read paid once).
__global__ void k_init(const float* __restrict__ W) {
    int i = blockIdx.x * blockDim.x + threadIdx.x;
    if (i < N_NODES) g_deg[i] = 1;
    if (i < (IN_F / 2) * OUT_F) {
        int k2 = i >> 5;
        int f  = i & 31;
        float w0 = W[f * IN_F + 2 * k2];
        float w1 = W[f * IN_F + 2 * k2 + 1];
        g_W2[i] = ((u64)__float_as_uint(w1) << 32) | (u64)__float_as_uint(w0);
    }
}

__global__ void k_deg_count(const int* __restrict__ ei) {
    int e = blockIdx.x * blockDim.x + threadIdx.x;
    if (e < N_EDGES) atomicAdd(&g_deg[ei[N_EDGES + e]], 1);
}

// ---------------------------------------------------------------------------
// K4: h = x @ W^T via packed f32x2 FMA, all operands staged through shared.
// One broadcast LDS.128 of an x row = two pre-packed (x[k],x[k+1]) b64 regs.
// 256 threads = 8 warps; warp register-blocks 8 nodes; lane = out feature.
#define NODES_PER_WARP 8
#define NODES_PER_BLK  64
#define FFMA2(acc, a, b) \
    asm("fma.rn.f32x2 %0, %1, %2, %0;" : "+l"(acc) : "l"(a), "l"(b))
#define CP_ASYNC16(saddr, gptr) \
    asm volatile("cp.async.cg.shared.global [%0], [%1], 16;" \
                 :: "r"(saddr), "l"(gptr) : "memory")

__global__ __launch_bounds__(256) void k_linear(const float* __restrict__ x) {
    __shared__ u64   sW2[IN_F / 2][OUT_F];          // 16KB, packed W pairs
    __shared__ float sx[NODES_PER_BLK][IN_F];       // 32KB x tile

    int tid = threadIdx.x;
    int node0 = blockIdx.x * NODES_PER_BLK;
    bool full = (node0 + NODES_PER_BLK <= N_NODES);

    // Stage x tile (2048 float4): cp.async for full blocks, guarded tail otherwise.
    const float4* xg = (const float4*)(x + (size_t)node0 * IN_F);
    float4* sx4 = (float4*)sx;
    if (full) {
        unsigned sbase;
        asm("{ .reg .u64 t; cvta.to.shared.u64 t, %1; cvt.u32.u64 %0, t; }"
            : "=r"(sbase) : "l"(sx4));
        #pragma unroll
        for (int i = 0; i < 8; i++) {
            int idx = tid + i * 256;
            CP_ASYNC16(sbase + idx * 16, xg + idx);
        }
        asm volatile("cp.async.commit_group;" ::: "memory");
    } else {
        #pragma unroll
        for (int i = 0; i < 8; i++) {
            int idx = tid + i * 256;
            sx4[idx] = (node0 + (idx >> 5) < N_NODES) ? xg[idx]
                                                      : make_float4(0.f, 0.f, 0.f, 0.f);
        }
    }

    // W pairs: coalesced u64 copy from g_W2 (L2-resident).
    {
        u64* sW = &sW2[0][0];
        #pragma unroll
        for (int i = 0; i < 8; i++)                 // 2048 u64 / 256 threads
            sW[tid + i * 256] = g_W2[tid + i * 256];
    }

    if (full) asm volatile("cp.async.wait_group 0;" ::: "memory");
    __syncthreads();

    int warp = tid >> 5;
    int f    = tid & 31;
    int nb   = warp * NODES_PER_WARP;

    u64 acc2[NODES_PER_WARP];                       // packed (even-k sum, odd-k sum)
    #pragma unroll
    for (int n = 0; n < NODES_PER_WARP; n++) acc2[n] = 0ull;

    #pragma unroll 8
    for (int k4 = 0; k4 < IN_F / 4; k4++) {
        u64 wa = sW2[2 * k4 + 0][f];                // LDS.64
        u64 wb = sW2[2 * k4 + 1][f];
        #pragma unroll
        for (int n = 0; n < NODES_PER_WARP; n++) {
            ulonglong2 xv = *(const ulonglong2*)&sx[nb + n][k4 * 4];  // broadcast LDS.128
            FFMA2(acc2[n], xv.x, wa);
            FFMA2(acc2[n], xv.y, wb);
        }
    }

    #pragma unroll
    for (int n = 0; n < NODES_PER_WARP; n++) {
        int node = node0 + nb + n;
        if (node < N_NODES) {
            float lo = __uint_as_float((unsigned)(acc2[n] & 0xFFFFFFFFull));
            float hi = __uint_as_float((unsigned)(acc2[n] >> 32));
            float d  = rsqrtf((float)g_deg[node]);
            float hd = (lo + hi) * d;
            g_hs [node * OUT_F + f] = hd;
            g_acc[node * OUT_F + f] = hd;           // self-loop term (dst norm at finalize)
        }
    }
}

// ---------------------------------------------------------------------------
// K5: edge scatter (R8 proven form). 8 lanes per edge; gather + red.v4.f32.
__global__ __launch_bounds__(256) void k_scatter(const int* __restrict__ ei) {
    int gtid = blockIdx.x * blockDim.x + threadIdx.x;
    int e  = gtid >> 3;
    int fq = (gtid & 7) * 4;

    int src = ei[e];
    int dst = ei[N_EDGES + e];

    float4 v = *(const float4*)(g_hs + src * OUT_F + fq);   // coalesced 128B/edge
    float* a = g_acc + dst * OUT_F + fq;
    asm volatile("red.global.add.v4.f32 [%0], {%1, %2, %3, %4};"
                 :: "l"(a), "f"(v.x), "f"(v.y), "f"(v.z), "f"(v.w)
                 : "memory");
}

// ---------------------------------------------------------------------------
// K6: out = g_acc * dis[node] + b   (plain coalesced float4 stores to d_out)
__global__ __launch_bounds__(256) void k_finalize(const float* __restrict__ b,
                                                  float* __restrict__ out) {
    int i = blockIdx.x * blockDim.x + threadIdx.x;    // float4 index
    if (i < N_NODES * OUT_F / 4) {
        int node = i >> 3;
        float d  = rsqrtf((float)g_deg[node]);
        float4 a = *((const float4*)g_acc + i);
        int fb = (i * 4) & (OUT_F - 1);
        a.x = fmaf(a.x, d, b[fb + 0]);
        a.y = fmaf(a.y, d, b[fb + 1]);
        a.z = fmaf(a.z, d, b[fb + 2]);
        a.w = fmaf(a.w, d, b[fb + 3]);
        *((float4*)out + i) = a;
    }
}

// ---------------------------------------------------------------------------
extern "C" void kernel_launch(void* const* d_in, const int* in_sizes, int n_in,
                              void* d_out, int out_size) {
    const float* x  = (const float*)d_in[0];
    const int*   ei = (const int*)d_in[1];     // int32 (harness downcasts int64)
    const float* W  = (const float*)d_in[2];
    const float* b  = (const float*)d_in[3];
    float*       out = (float*)d_out;

    (void)in_sizes; (void)n_in; (void)out_size;

    k_init     <<<(N_NODES + 255) / 256, 256>>>(W);
    k_deg_count<<<(N_EDGES + 255) / 256, 256>>>(ei);
    k_linear   <<<(N_NODES + NODES_PER_BLK - 1) / NODES_PER_BLK, 256>>>(x);
    k_scatter  <<<(N_EDGES * 8) / 256, 256>>>(ei);
    k_finalize <<<(N_NODES * OUT_F / 4 + 255) / 256, 256>>>(b, out);
}